// round 1
// baseline (speedup 1.0000x reference)
#include <cuda_runtime.h>
#include <cstdint>

// Problem dims (fixed by the reference)
#define S_DIM 2048
#define B_DIM 256
#define D_DIM 128
#define M_TOTAL (S_DIM * B_DIM)          // 524288 token rows
#define BD (B_DIM * D_DIM)               // 32768 scan lanes

// Scratch: h = relu(src@Wm+bm) [S*B,128]; p = [g|k] = h@[Wb1|Wb2] [S*B,256]
__device__ float g_h[(size_t)M_TOTAL * D_DIM];       // 268 MB
__device__ float g_p[(size_t)M_TOTAL * 2 * D_DIM];   // 536 MB

__device__ __forceinline__ unsigned f2tf32(float f) {
    unsigned r;
    asm("cvt.rna.tf32.f32 %0, %1;" : "=r"(r) : "f"(f));
    return r;
}

// ---------------------------------------------------------------------------
// Tiled tf32 GEMM: C[row0:row0+128, col_off:col_off+128] = A[128,128] @ Bw[128,128]
// A rows contiguous with stride 128 (both src and h have this layout).
// Bw is a contiguous 128x128 fp32 matrix (k-major).
// If RELU_BIAS: C = relu(A@Bw + bias[col]).
// Block: 256 threads (8 warps as 4x2), warp tile 32x64, mma m16n8k8 tf32.
// ---------------------------------------------------------------------------
template <bool RELU_BIAS>
__global__ void gemm128(const float* __restrict__ A,
                        const float* __restrict__ Bw,
                        const float* __restrict__ bias,
                        float* __restrict__ C,
                        int ldc, int col_off)
{
    extern __shared__ unsigned smem_u[];
    unsigned* sA = smem_u;                 // [128][132]
    unsigned* sB = smem_u + 128 * 132;     // [128][132]

    const int tid = threadIdx.x;
    const size_t row0 = (size_t)blockIdx.x * 128;

    // Load A tile (128x128 floats = 4096 float4) and Bw, converting to tf32 bits.
    const float4* A4 = (const float4*)(A + row0 * 128);
    const float4* B4 = (const float4*)Bw;
#pragma unroll
    for (int i = 0; i < 16; i++) {
        int v = i * 256 + tid;          // 0..4095
        int r = v >> 5;                 // row 0..127
        int c4 = v & 31;                // float4 col 0..31
        float4 fa = A4[v];
        unsigned* da = sA + r * 132 + c4 * 4;
        da[0] = f2tf32(fa.x); da[1] = f2tf32(fa.y);
        da[2] = f2tf32(fa.z); da[3] = f2tf32(fa.w);
        float4 fb = B4[v];
        unsigned* db = sB + r * 132 + c4 * 4;
        db[0] = f2tf32(fb.x); db[1] = f2tf32(fb.y);
        db[2] = f2tf32(fb.z); db[3] = f2tf32(fb.w);
    }
    __syncthreads();

    const int lane = tid & 31;
    const int warp = tid >> 5;
    const int wm = warp & 3;            // 4 warps along M
    const int wn = warp >> 2;           // 2 warps along N
    const int mb = wm * 32;
    const int nb = wn * 64;
    const int grp = lane >> 2;          // 0..7
    const int thr = lane & 3;           // 0..3

    float acc[2][8][4];
#pragma unroll
    for (int mt = 0; mt < 2; mt++)
#pragma unroll
        for (int nt = 0; nt < 8; nt++)
#pragma unroll
            for (int q = 0; q < 4; q++) acc[mt][nt][q] = 0.f;

#pragma unroll
    for (int k0 = 0; k0 < 128; k0 += 8) {
        unsigned af[2][4];
#pragma unroll
        for (int mt = 0; mt < 2; mt++) {
            int r = mb + mt * 16 + grp;
            af[mt][0] = sA[r * 132 + k0 + thr];
            af[mt][1] = sA[(r + 8) * 132 + k0 + thr];
            af[mt][2] = sA[r * 132 + k0 + thr + 4];
            af[mt][3] = sA[(r + 8) * 132 + k0 + thr + 4];
        }
        unsigned bf[8][2];
#pragma unroll
        for (int nt = 0; nt < 8; nt++) {
            int c = nb + nt * 8 + grp;
            bf[nt][0] = sB[(k0 + thr) * 132 + c];
            bf[nt][1] = sB[(k0 + thr + 4) * 132 + c];
        }
#pragma unroll
        for (int mt = 0; mt < 2; mt++)
#pragma unroll
            for (int nt = 0; nt < 8; nt++) {
                asm volatile(
                    "mma.sync.aligned.m16n8k8.row.col.f32.tf32.tf32.f32 "
                    "{%0,%1,%2,%3}, {%4,%5,%6,%7}, {%8,%9}, {%0,%1,%2,%3};"
                    : "+f"(acc[mt][nt][0]), "+f"(acc[mt][nt][1]),
                      "+f"(acc[mt][nt][2]), "+f"(acc[mt][nt][3])
                    : "r"(af[mt][0]), "r"(af[mt][1]), "r"(af[mt][2]), "r"(af[mt][3]),
                      "r"(bf[nt][0]), "r"(bf[nt][1]));
            }
    }

    // Epilogue: fragment c0,c1 -> (row, 2*thr..+1); c2,c3 -> (row+8, ...)
#pragma unroll
    for (int mt = 0; mt < 2; mt++) {
#pragma unroll
        for (int nt = 0; nt < 8; nt++) {
            int r = mb + mt * 16 + grp;
            int c = nb + nt * 8 + 2 * thr;
            float2 v0 = make_float2(acc[mt][nt][0], acc[mt][nt][1]);
            float2 v1 = make_float2(acc[mt][nt][2], acc[mt][nt][3]);
            if (RELU_BIAS) {
                float b0 = bias[c], b1 = bias[c + 1];
                v0.x = fmaxf(v0.x + b0, 0.f);
                v0.y = fmaxf(v0.y + b1, 0.f);
                v1.x = fmaxf(v1.x + b0, 0.f);
                v1.y = fmaxf(v1.y + b1, 0.f);
            }
            *(float2*)(C + (row0 + r) * ldc + col_off + c) = v0;
            *(float2*)(C + (row0 + r + 8) * ldc + col_off + c) = v1;
        }
    }
}

// ---------------------------------------------------------------------------
// Scan: out[s,b,d] = sum_{j<=s} ( h[j,b,d] + relu(g[j,b,d] + k[j+1,b,d] + bb[d]) )
// p layout: p[token = s*B+b][0:128] = g, [128:256] = k. One thread per (b,d).
// ---------------------------------------------------------------------------
__global__ void scan_kernel(const float* __restrict__ bb, float* __restrict__ out)
{
    const int j = blockIdx.x * blockDim.x + threadIdx.x;   // 0..32767
    const int b = j >> 7;
    const int d = j & 127;
    const float bias = bb[d];
    const float* __restrict__ hp = g_h;
    const float* __restrict__ pp = g_p;
    const size_t gbase = (size_t)b * 256 + d;              // within-row offset for g
    float acc = 0.f;
#pragma unroll 4
    for (int s = 0; s < S_DIM - 1; s++) {
        float hv = hp[(size_t)s * BD + j];
        float gv = pp[(size_t)s * (2 * BD) + gbase];
        float kv = pp[(size_t)(s + 1) * (2 * BD) + gbase + 128];
        float t = fmaxf(gv + kv + bias, 0.f);
        acc += hv + t;
        out[(size_t)s * BD + j] = acc;
    }
}

extern "C" void kernel_launch(void* const* d_in, const int* in_sizes, int n_in,
                              void* d_out, int out_size)
{
    const float* src = (const float*)d_in[0];   // [S, B, D]
    const float* Wm  = (const float*)d_in[1];   // [D, D]
    const float* bm  = (const float*)d_in[2];   // [D]
    const float* Wb  = (const float*)d_in[3];   // [2D, D]
    const float* bb  = (const float*)d_in[4];   // [D]
    float* out = (float*)d_out;                 // [S-1, B, D]

    void* hp_v = nullptr;
    void* pp_v = nullptr;
    cudaGetSymbolAddress(&hp_v, g_h);
    cudaGetSymbolAddress(&pp_v, g_p);
    float* hp = (float*)hp_v;
    float* pp = (float*)pp_v;

    const int smem_bytes = 2 * 128 * 132 * sizeof(unsigned);   // 135168
    cudaFuncSetAttribute((const void*)gemm128<true>,
                         cudaFuncAttributeMaxDynamicSharedMemorySize, smem_bytes);
    cudaFuncSetAttribute((const void*)gemm128<false>,
                         cudaFuncAttributeMaxDynamicSharedMemorySize, smem_bytes);

    const int grid = M_TOTAL / 128;   // 4096

    // h = relu(src @ Wm + bm)
    gemm128<true><<<grid, 256, smem_bytes>>>(src, Wm, bm, hp, 128, 0);
    // g = h @ Wb[0:128, :]   -> p[:, 0:128]
    gemm128<false><<<grid, 256, smem_bytes>>>(hp, Wb, nullptr, pp, 256, 0);
    // k = h @ Wb[128:256, :] -> p[:, 128:256]
    gemm128<false><<<grid, 256, smem_bytes>>>(hp, Wb + 128 * 128, nullptr, pp, 256, 128);
    // cumulative context
    scan_kernel<<<BD / 256, 256>>>(bb, out);
}

// round 2
// speedup vs baseline: 1.2846x; 1.2846x over previous
#include <cuda_runtime.h>
#include <cstdint>

// Problem dims (fixed by the reference)
#define S_DIM 2048
#define B_DIM 256
#define D_DIM 128
#define M_TOTAL (S_DIM * B_DIM)          // 524288 token rows
#define BD (B_DIM * D_DIM)               // 32768 scan lanes
#define SM1 (S_DIM - 1)                  // 2047
#define NCHUNK 32
#define CHUNK_LEN 64                     // 32*64 >= 2047

// Scratch
__device__ float g_h[(size_t)M_TOTAL * D_DIM];        // 268 MB : h = relu(src@Wm+bm)
__device__ float g_u[(size_t)SM1 * B_DIM * D_DIM];    // 268 MB : u = h[s] + relu(g+k'+bb)
__device__ float g_tot[NCHUNK * BD];                  // 4 MB   : per-chunk sums

__device__ __forceinline__ unsigned f2tf32(float f) {
    unsigned r;
    asm("cvt.rna.tf32.f32 %0, %1;" : "=r"(r) : "f"(f));
    return r;
}

// ---------------------------------------------------------------------------
// GEMM1: h[128 rows] = relu(src @ Wm + bm). Same as round-1 gemm128<true>.
// Block: 256 threads (8 warps as 4x2), warp tile 32x64, mma m16n8k8 tf32.
// ---------------------------------------------------------------------------
__global__ void gemm_map(const float* __restrict__ A,
                         const float* __restrict__ Bw,
                         const float* __restrict__ bias,
                         float* __restrict__ C)
{
    extern __shared__ unsigned smem_u[];
    unsigned* sA = smem_u;                 // [128][132]
    unsigned* sB = smem_u + 128 * 132;     // [128][132]

    const int tid = threadIdx.x;
    const size_t row0 = (size_t)blockIdx.x * 128;

    const float4* A4 = (const float4*)(A + row0 * 128);
    const float4* B4 = (const float4*)Bw;
#pragma unroll
    for (int i = 0; i < 16; i++) {
        int v = i * 256 + tid;
        int r = v >> 5;
        int c4 = v & 31;
        float4 fa = A4[v];
        unsigned* da = sA + r * 132 + c4 * 4;
        da[0] = f2tf32(fa.x); da[1] = f2tf32(fa.y);
        da[2] = f2tf32(fa.z); da[3] = f2tf32(fa.w);
        float4 fb = B4[v];
        unsigned* db = sB + r * 132 + c4 * 4;
        db[0] = f2tf32(fb.x); db[1] = f2tf32(fb.y);
        db[2] = f2tf32(fb.z); db[3] = f2tf32(fb.w);
    }
    __syncthreads();

    const int lane = tid & 31;
    const int warp = tid >> 5;
    const int mb = (warp & 3) * 32;
    const int nb = (warp >> 2) * 64;
    const int grp = lane >> 2;
    const int thr = lane & 3;

    float acc[2][8][4];
#pragma unroll
    for (int mt = 0; mt < 2; mt++)
#pragma unroll
        for (int nt = 0; nt < 8; nt++)
#pragma unroll
            for (int q = 0; q < 4; q++) acc[mt][nt][q] = 0.f;

#pragma unroll
    for (int k0 = 0; k0 < 128; k0 += 8) {
        unsigned af[2][4];
#pragma unroll
        for (int mt = 0; mt < 2; mt++) {
            int r = mb + mt * 16 + grp;
            af[mt][0] = sA[r * 132 + k0 + thr];
            af[mt][1] = sA[(r + 8) * 132 + k0 + thr];
            af[mt][2] = sA[r * 132 + k0 + thr + 4];
            af[mt][3] = sA[(r + 8) * 132 + k0 + thr + 4];
        }
        unsigned bf[8][2];
#pragma unroll
        for (int nt = 0; nt < 8; nt++) {
            int c = nb + nt * 8 + grp;
            bf[nt][0] = sB[(k0 + thr) * 132 + c];
            bf[nt][1] = sB[(k0 + thr + 4) * 132 + c];
        }
#pragma unroll
        for (int mt = 0; mt < 2; mt++)
#pragma unroll
            for (int nt = 0; nt < 8; nt++) {
                asm volatile(
                    "mma.sync.aligned.m16n8k8.row.col.f32.tf32.tf32.f32 "
                    "{%0,%1,%2,%3}, {%4,%5,%6,%7}, {%8,%9}, {%0,%1,%2,%3};"
                    : "+f"(acc[mt][nt][0]), "+f"(acc[mt][nt][1]),
                      "+f"(acc[mt][nt][2]), "+f"(acc[mt][nt][3])
                    : "r"(af[mt][0]), "r"(af[mt][1]), "r"(af[mt][2]), "r"(af[mt][3]),
                      "r"(bf[nt][0]), "r"(bf[nt][1]));
            }
    }

#pragma unroll
    for (int mt = 0; mt < 2; mt++) {
#pragma unroll
        for (int nt = 0; nt < 8; nt++) {
            int r = mb + mt * 16 + grp;
            int c = nb + nt * 8 + 2 * thr;
            float b0 = bias[c], b1 = bias[c + 1];
            float2 v0, v1;
            v0.x = fmaxf(acc[mt][nt][0] + b0, 0.f);
            v0.y = fmaxf(acc[mt][nt][1] + b1, 0.f);
            v1.x = fmaxf(acc[mt][nt][2] + b0, 0.f);
            v1.y = fmaxf(acc[mt][nt][3] + b1, 0.f);
            *(float2*)(C + (row0 + r) * 128 + c) = v0;
            *(float2*)(C + (row0 + r + 8) * 128 + c) = v1;
        }
    }
}

// ---------------------------------------------------------------------------
// Fused bracket: u[token] = h[token] + relu( h[token]@Wb1 + h[token+256]@Wb2 + bb )
// token = s*B + b, valid for s < S-1, i.e. tokens [0, (S-1)*B).
// Two accumulation phases over the same accumulators, reusing one A smem tile.
// smem: sA[128][132] + sW1[128][132] + sW2[128][132] = 198 KB.
// ---------------------------------------------------------------------------
__global__ void gemm_bracket(const float* __restrict__ h,
                             const float* __restrict__ Wb,
                             const float* __restrict__ bb,
                             float* __restrict__ u)
{
    extern __shared__ unsigned smem_u[];
    unsigned* sA  = smem_u;                  // [128][132]
    unsigned* sW1 = smem_u + 128 * 132;      // [128][132]
    unsigned* sW2 = smem_u + 2 * 128 * 132;  // [128][132]

    const int tid = threadIdx.x;
    const size_t row0 = (size_t)blockIdx.x * 128;

    // Load A1 = h[row0 .. row0+127], W1 = Wb[0:128], W2 = Wb[128:256]
    {
        const float4* A4 = (const float4*)(h + row0 * 128);
        const float4* W14 = (const float4*)Wb;
        const float4* W24 = (const float4*)(Wb + 128 * 128);
#pragma unroll
        for (int i = 0; i < 16; i++) {
            int v = i * 256 + tid;
            int r = v >> 5;
            int c4 = v & 31;
            float4 f = A4[v];
            unsigned* d = sA + r * 132 + c4 * 4;
            d[0] = f2tf32(f.x); d[1] = f2tf32(f.y); d[2] = f2tf32(f.z); d[3] = f2tf32(f.w);
            f = W14[v];
            d = sW1 + r * 132 + c4 * 4;
            d[0] = f2tf32(f.x); d[1] = f2tf32(f.y); d[2] = f2tf32(f.z); d[3] = f2tf32(f.w);
            f = W24[v];
            d = sW2 + r * 132 + c4 * 4;
            d[0] = f2tf32(f.x); d[1] = f2tf32(f.y); d[2] = f2tf32(f.z); d[3] = f2tf32(f.w);
        }
    }
    __syncthreads();

    const int lane = tid & 31;
    const int warp = tid >> 5;
    const int mb = (warp & 3) * 32;
    const int nb = (warp >> 2) * 64;
    const int grp = lane >> 2;
    const int thr = lane & 3;

    float acc[2][8][4];
#pragma unroll
    for (int mt = 0; mt < 2; mt++)
#pragma unroll
        for (int nt = 0; nt < 8; nt++)
#pragma unroll
            for (int q = 0; q < 4; q++) acc[mt][nt][q] = 0.f;

    // Phase 1: acc += A1 @ W1.  Phase 2: reload sA with A2, acc += A2 @ W2.
#pragma unroll
    for (int phase = 0; phase < 2; phase++) {
        const unsigned* sW = phase ? sW2 : sW1;
#pragma unroll
        for (int k0 = 0; k0 < 128; k0 += 8) {
            unsigned af[2][4];
#pragma unroll
            for (int mt = 0; mt < 2; mt++) {
                int r = mb + mt * 16 + grp;
                af[mt][0] = sA[r * 132 + k0 + thr];
                af[mt][1] = sA[(r + 8) * 132 + k0 + thr];
                af[mt][2] = sA[r * 132 + k0 + thr + 4];
                af[mt][3] = sA[(r + 8) * 132 + k0 + thr + 4];
            }
            unsigned bf[8][2];
#pragma unroll
            for (int nt = 0; nt < 8; nt++) {
                int c = nb + nt * 8 + grp;
                bf[nt][0] = sW[(k0 + thr) * 132 + c];
                bf[nt][1] = sW[(k0 + thr + 4) * 132 + c];
            }
#pragma unroll
            for (int mt = 0; mt < 2; mt++)
#pragma unroll
                for (int nt = 0; nt < 8; nt++) {
                    asm volatile(
                        "mma.sync.aligned.m16n8k8.row.col.f32.tf32.tf32.f32 "
                        "{%0,%1,%2,%3}, {%4,%5,%6,%7}, {%8,%9}, {%0,%1,%2,%3};"
                        : "+f"(acc[mt][nt][0]), "+f"(acc[mt][nt][1]),
                          "+f"(acc[mt][nt][2]), "+f"(acc[mt][nt][3])
                        : "r"(af[mt][0]), "r"(af[mt][1]), "r"(af[mt][2]), "r"(af[mt][3]),
                          "r"(bf[nt][0]), "r"(bf[nt][1]));
                }
        }
        if (phase == 0) {
            __syncthreads();
            // Reload sA with A2 = h[row0+256 .. row0+383] (same batch lanes, s+1)
            const float4* A4 = (const float4*)(h + (row0 + 256) * 128);
#pragma unroll
            for (int i = 0; i < 16; i++) {
                int v = i * 256 + tid;
                int r = v >> 5;
                int c4 = v & 31;
                float4 f = A4[v];
                unsigned* d = sA + r * 132 + c4 * 4;
                d[0] = f2tf32(f.x); d[1] = f2tf32(f.y); d[2] = f2tf32(f.z); d[3] = f2tf32(f.w);
            }
            __syncthreads();
        }
    }

    // Epilogue: u = h[row] + relu(acc + bb[c]); h rows re-read (L1/L2 hit).
#pragma unroll
    for (int mt = 0; mt < 2; mt++) {
#pragma unroll
        for (int nt = 0; nt < 8; nt++) {
            int r = mb + mt * 16 + grp;
            int c = nb + nt * 8 + 2 * thr;
            float b0 = bb[c], b1 = bb[c + 1];
            float2 h0 = *(const float2*)(h + (row0 + r) * 128 + c);
            float2 h1 = *(const float2*)(h + (row0 + r + 8) * 128 + c);
            float2 v0, v1;
            v0.x = h0.x + fmaxf(acc[mt][nt][0] + b0, 0.f);
            v0.y = h0.y + fmaxf(acc[mt][nt][1] + b1, 0.f);
            v1.x = h1.x + fmaxf(acc[mt][nt][2] + b0, 0.f);
            v1.y = h1.y + fmaxf(acc[mt][nt][3] + b1, 0.f);
            *(float2*)(u + (row0 + r) * 128 + c) = v0;
            *(float2*)(u + (row0 + r + 8) * 128 + c) = v1;
        }
    }
}

// ---------------------------------------------------------------------------
// Chunked scan over s (2047 steps -> 32 chunks of <=64).
// Phase A: per-chunk sums. Phase C: prefix from totals + local cumsum.
// lane j = (bid & 127)*256 + tid (0..32767), chunk c = bid >> 7.
// ---------------------------------------------------------------------------
__global__ void scan_partial(const float* __restrict__ u, float* __restrict__ tot)
{
    const int j = ((blockIdx.x & 127) << 8) + threadIdx.x;
    const int c = blockIdx.x >> 7;
    const int s0 = c * CHUNK_LEN;
    const int s1 = min(s0 + CHUNK_LEN, SM1);
    float a = 0.f;
#pragma unroll 4
    for (int s = s0; s < s1; s++) a += u[(size_t)s * BD + j];
    tot[c * BD + j] = a;
}

__global__ void scan_final(const float* __restrict__ u,
                           const float* __restrict__ tot,
                           float* __restrict__ out)
{
    const int j = ((blockIdx.x & 127) << 8) + threadIdx.x;
    const int c = blockIdx.x >> 7;
    const int s0 = c * CHUNK_LEN;
    const int s1 = min(s0 + CHUNK_LEN, SM1);
    float acc = 0.f;
    for (int cc = 0; cc < c; cc++) acc += tot[cc * BD + j];
#pragma unroll 4
    for (int s = s0; s < s1; s++) {
        acc += u[(size_t)s * BD + j];
        out[(size_t)s * BD + j] = acc;
    }
}

extern "C" void kernel_launch(void* const* d_in, const int* in_sizes, int n_in,
                              void* d_out, int out_size)
{
    const float* src = (const float*)d_in[0];   // [S, B, D]
    const float* Wm  = (const float*)d_in[1];   // [D, D]
    const float* bm  = (const float*)d_in[2];   // [D]
    const float* Wb  = (const float*)d_in[3];   // [2D, D]
    const float* bb  = (const float*)d_in[4];   // [D]
    float* out = (float*)d_out;                 // [S-1, B, D]

    void *hp_v, *up_v, *tp_v;
    cudaGetSymbolAddress(&hp_v, g_h);
    cudaGetSymbolAddress(&up_v, g_u);
    cudaGetSymbolAddress(&tp_v, g_tot);
    float* hp = (float*)hp_v;
    float* up = (float*)up_v;
    float* tp = (float*)tp_v;

    const int smem_map = 2 * 128 * 132 * sizeof(unsigned);      // 135168
    const int smem_brk = 3 * 128 * 132 * sizeof(unsigned);      // 202752
    cudaFuncSetAttribute((const void*)gemm_map,
                         cudaFuncAttributeMaxDynamicSharedMemorySize, smem_map);
    cudaFuncSetAttribute((const void*)gemm_bracket,
                         cudaFuncAttributeMaxDynamicSharedMemorySize, smem_brk);

    // h = relu(src @ Wm + bm)   (all S*B tokens)
    gemm_map<<<M_TOTAL / 128, 256, smem_map>>>(src, Wm, bm, hp);
    // u = h[s] + relu(h[s]@Wb1 + h[s+1]@Wb2 + bb)  (tokens of s < S-1)
    gemm_bracket<<<(SM1 * B_DIM) / 128, 256, smem_brk>>>(hp, Wb, bb, up);
    // chunked cumsum over s
    scan_partial<<<NCHUNK * (BD / 256), 256>>>(up, tp);
    scan_final<<<NCHUNK * (BD / 256), 256>>>(up, tp, out);
}

// round 3
// speedup vs baseline: 1.3743x; 1.0699x over previous
#include <cuda_runtime.h>
#include <cstdint>

#define S_DIM 2048
#define B_DIM 256
#define D_DIM 128
#define M_TOTAL (S_DIM * B_DIM)          // 524288 token rows
#define BD (B_DIM * D_DIM)               // 32768 scan lanes
#define SM1 (S_DIM - 1)                  // 2047
#define NCHUNK 32
#define CHUNK_LEN 64
#define PAD 132                           // smem row stride (floats), conflict-free

// Scratch
__device__ float g_h[(size_t)M_TOTAL * D_DIM];        // 268 MB
__device__ float g_u[(size_t)SM1 * B_DIM * D_DIM];    // 268 MB
__device__ float g_tot[NCHUNK * BD];                  // 4 MB

__device__ __forceinline__ unsigned f2tf32(float f) {
    unsigned r;
    asm("cvt.rna.tf32.f32 %0, %1;" : "=r"(r) : "f"(f));
    return r;
}

#define MMA_TF32(acc, af, bf)                                                  \
    asm volatile(                                                              \
        "mma.sync.aligned.m16n8k8.row.col.f32.tf32.tf32.f32 "                  \
        "{%0,%1,%2,%3}, {%4,%5,%6,%7}, {%8,%9}, {%0,%1,%2,%3};"                \
        : "+f"(acc[0]), "+f"(acc[1]), "+f"(acc[2]), "+f"(acc[3])               \
        : "r"(af[0]), "r"(af[1]), "r"(af[2]), "r"(af[3]),                      \
          "r"(bf[0]), "r"(bf[1]))

// Stage a tile of n*256 float4 from global into registers (coalesced).
template <int N4>
__device__ __forceinline__ void ldg_tile(const float4* __restrict__ base,
                                         float4* regs, int tid) {
#pragma unroll
    for (int i = 0; i < N4; i++) regs[i] = base[i * 256 + tid];
}

// Store staged registers to smem as tf32 (rows of 128 floats, stride PAD).
template <int N4>
__device__ __forceinline__ void sts_tile(unsigned* s, const float4* regs, int tid) {
#pragma unroll
    for (int i = 0; i < N4; i++) {
        int v = i * 256 + tid;
        int r = v >> 5;
        int c4 = v & 31;
        unsigned* d = s + r * PAD + c4 * 4;
        d[0] = f2tf32(regs[i].x); d[1] = f2tf32(regs[i].y);
        d[2] = f2tf32(regs[i].z); d[3] = f2tf32(regs[i].w);
    }
}

// ---------------------------------------------------------------------------
// Persistent map GEMM: h = relu(src @ Wm + bm), 128-row tiles.
// smem: sW[128][PAD], sA[2][128][PAD] = 202752 B. One sync per iteration.
// ---------------------------------------------------------------------------
__global__ void gemm_map(const float* __restrict__ A,
                         const float* __restrict__ Bw,
                         const float* __restrict__ bias,
                         float* __restrict__ C)
{
    extern __shared__ unsigned smem_u[];
    unsigned* sW = smem_u;                       // [128][PAD]
    unsigned* sA[2] = { smem_u + 128 * PAD, smem_u + 2 * 128 * PAD };

    const int tid = threadIdx.x;
    const int bid = blockIdx.x;
    // tile range: 4096 tiles over 148 CTAs
    const int base = bid * 27 + (bid < 100 ? bid : 100);
    const int cnt  = 27 + (bid < 100 ? 1 : 0);

    // Prologue: weights + first A tile
    {
        float4 rw[16];
        ldg_tile<16>((const float4*)Bw, rw, tid);
        float4 ra[16];
        ldg_tile<16>((const float4*)(A + (size_t)base * 128 * 128), ra, tid);
        sts_tile<16>(sW, rw, tid);
        sts_tile<16>(sA[0], ra, tid);
    }
    __syncthreads();

    const int lane = tid & 31;
    const int warp = tid >> 5;
    const int mb = (warp & 3) * 32;
    const int nb = (warp >> 2) * 64;
    const int grp = lane >> 2;
    const int thr = lane & 3;

    int cur = 0;
    for (int it = 0; it < cnt; it++) {
        const size_t t = (size_t)(base + it);
        const bool pref = (it + 1 < cnt);
        float4 regs[16];
        if (pref)
            ldg_tile<16>((const float4*)(A + (t + 1) * 128 * 128), regs, tid);

        float acc[2][8][4];
#pragma unroll
        for (int mt = 0; mt < 2; mt++)
#pragma unroll
            for (int nt = 0; nt < 8; nt++)
#pragma unroll
                for (int q = 0; q < 4; q++) acc[mt][nt][q] = 0.f;

        const unsigned* sAc = sA[cur];
#pragma unroll
        for (int k0 = 0; k0 < 128; k0 += 8) {
            unsigned af[2][4];
#pragma unroll
            for (int mt = 0; mt < 2; mt++) {
                int r = mb + mt * 16 + grp;
                af[mt][0] = sAc[r * PAD + k0 + thr];
                af[mt][1] = sAc[(r + 8) * PAD + k0 + thr];
                af[mt][2] = sAc[r * PAD + k0 + thr + 4];
                af[mt][3] = sAc[(r + 8) * PAD + k0 + thr + 4];
            }
            unsigned bf[8][2];
#pragma unroll
            for (int nt = 0; nt < 8; nt++) {
                int c = nb + nt * 8 + grp;
                bf[nt][0] = sW[(k0 + thr) * PAD + c];
                bf[nt][1] = sW[(k0 + thr + 4) * PAD + c];
            }
#pragma unroll
            for (int mt = 0; mt < 2; mt++)
#pragma unroll
                for (int nt = 0; nt < 8; nt++)
                    MMA_TF32(acc[mt][nt], af[mt], bf[nt]);
        }

        // Epilogue: h = relu(acc + bias)
        const size_t row0 = t * 128;
#pragma unroll
        for (int mt = 0; mt < 2; mt++) {
#pragma unroll
            for (int nt = 0; nt < 8; nt++) {
                int r = mb + mt * 16 + grp;
                int c = nb + nt * 8 + 2 * thr;
                float b0 = bias[c], b1 = bias[c + 1];
                float2 v0, v1;
                v0.x = fmaxf(acc[mt][nt][0] + b0, 0.f);
                v0.y = fmaxf(acc[mt][nt][1] + b1, 0.f);
                v1.x = fmaxf(acc[mt][nt][2] + b0, 0.f);
                v1.y = fmaxf(acc[mt][nt][3] + b1, 0.f);
                *(float2*)(C + (row0 + r) * 128 + c) = v0;
                *(float2*)(C + (row0 + r + 8) * 128 + c) = v1;
            }
        }

        __syncthreads();                 // all reads of sA[cur^1] from prev iter done
        if (pref) sts_tile<16>(sA[cur ^ 1], regs, tid);
        __syncthreads();                 // staged tile visible
        cur ^= 1;
    }
}

// ---------------------------------------------------------------------------
// Persistent fused bracket: u[tok] = h[tok] + relu(h[tok]@Wb1 + h[tok+256]@Wb2 + bb)
// 64-row tiles; +1 s-step = +4 tiles. Each CTA walks a stride-4 chain so A[t+4]
// is reused as the next iteration's A[t] (h read once).
// smem: sW1,sW2 [128][PAD] + sA[2][64][PAD] = 202752 B.
// ---------------------------------------------------------------------------
__global__ void gemm_bracket(const float* __restrict__ h,
                             const float* __restrict__ Wb,
                             const float* __restrict__ bb,
                             float* __restrict__ u)
{
    extern __shared__ unsigned smem_u[];
    unsigned* sW1 = smem_u;                          // [128][PAD]
    unsigned* sW2 = smem_u + 128 * PAD;              // [128][PAD]
    unsigned* sA[2] = { smem_u + 2 * 128 * PAD,
                        smem_u + 2 * 128 * PAD + 64 * PAD };

    const int tid = threadIdx.x;
    const int bid = blockIdx.x;
    const int res = bid & 3;                  // residue of the stride-4 chain
    const int j   = bid >> 2;                 // 0..36
    // 2047 chain positions over 37 CTAs: 12 CTAs get 56, 25 get 55
    const int i0  = j * 55 + (j < 12 ? j : 12);
    const int cnt = 55 + (j < 12 ? 1 : 0);

    // Prologue: weights + A[t0], A[t0+4]
    {
        float4 rw1[16], rw2[16];
        ldg_tile<16>((const float4*)Wb, rw1, tid);
        ldg_tile<16>((const float4*)(Wb + 128 * 128), rw2, tid);
        const size_t t0 = (size_t)res + 4 * (size_t)i0;
        float4 ra0[8], ra1[8];
        ldg_tile<8>((const float4*)(h + t0 * 64 * 128), ra0, tid);
        ldg_tile<8>((const float4*)(h + (t0 + 4) * 64 * 128), ra1, tid);
        sts_tile<16>(sW1, rw1, tid);
        sts_tile<16>(sW2, rw2, tid);
        sts_tile<8>(sA[0], ra0, tid);
        sts_tile<8>(sA[1], ra1, tid);
    }
    __syncthreads();

    const int lane = tid & 31;
    const int warp = tid >> 5;
    const int mb = (warp & 1) * 32;           // 2 warps along M (64 rows)
    const int nb = (warp >> 1) * 32;          // 4 warps along N (128 cols)
    const int grp = lane >> 2;
    const int thr = lane & 3;

    int cur = 0;
    for (int it = 0; it < cnt; it++) {
        const size_t t = (size_t)res + 4 * (size_t)(i0 + it);
        const bool pref = (it + 1 < cnt);
        float4 regs[8];
        if (pref)                              // A[t+8] = next iter's A[t+4]
            ldg_tile<8>((const float4*)(h + (t + 8) * 64 * 128), regs, tid);

        float acc[2][4][4];
#pragma unroll
        for (int mt = 0; mt < 2; mt++)
#pragma unroll
            for (int nt = 0; nt < 4; nt++)
#pragma unroll
                for (int q = 0; q < 4; q++) acc[mt][nt][q] = 0.f;

        // Phase 1: A[t] @ W1 ; Phase 2: A[t+4] @ W2
#pragma unroll
        for (int phase = 0; phase < 2; phase++) {
            const unsigned* sAc = sA[cur ^ phase];
            const unsigned* sW  = phase ? sW2 : sW1;
#pragma unroll
            for (int k0 = 0; k0 < 128; k0 += 8) {
                unsigned af[2][4];
#pragma unroll
                for (int mt = 0; mt < 2; mt++) {
                    int r = mb + mt * 16 + grp;
                    af[mt][0] = sAc[r * PAD + k0 + thr];
                    af[mt][1] = sAc[(r + 8) * PAD + k0 + thr];
                    af[mt][2] = sAc[r * PAD + k0 + thr + 4];
                    af[mt][3] = sAc[(r + 8) * PAD + k0 + thr + 4];
                }
                unsigned bf[4][2];
#pragma unroll
                for (int nt = 0; nt < 4; nt++) {
                    int c = nb + nt * 8 + grp;
                    bf[nt][0] = sW[(k0 + thr) * PAD + c];
                    bf[nt][1] = sW[(k0 + thr + 4) * PAD + c];
                }
#pragma unroll
                for (int mt = 0; mt < 2; mt++)
#pragma unroll
                    for (int nt = 0; nt < 4; nt++)
                        MMA_TF32(acc[mt][nt], af[mt], bf[nt]);
            }
        }

        // Epilogue: u = h(tf32 copy from sA[cur]) + relu(acc + bb)
        const size_t row0 = t * 64;
        const unsigned* sAc = sA[cur];
#pragma unroll
        for (int mt = 0; mt < 2; mt++) {
#pragma unroll
            for (int nt = 0; nt < 4; nt++) {
                int r = mb + mt * 16 + grp;
                int c = nb + nt * 8 + 2 * thr;
                float b0 = bb[c], b1 = bb[c + 1];
                float h00 = __uint_as_float(sAc[r * PAD + c]);
                float h01 = __uint_as_float(sAc[r * PAD + c + 1]);
                float h10 = __uint_as_float(sAc[(r + 8) * PAD + c]);
                float h11 = __uint_as_float(sAc[(r + 8) * PAD + c + 1]);
                float2 v0, v1;
                v0.x = h00 + fmaxf(acc[mt][nt][0] + b0, 0.f);
                v0.y = h01 + fmaxf(acc[mt][nt][1] + b1, 0.f);
                v1.x = h10 + fmaxf(acc[mt][nt][2] + b0, 0.f);
                v1.y = h11 + fmaxf(acc[mt][nt][3] + b1, 0.f);
                *(float2*)(u + (row0 + r) * 128 + c) = v0;
                *(float2*)(u + (row0 + r + 8) * 128 + c) = v1;
            }
        }

        __syncthreads();                  // reads of sA[cur] done (phase1 + epilogue)
        if (pref) sts_tile<8>(sA[cur], regs, tid);   // overwrite A[t] with A[t+8]
        __syncthreads();
        cur ^= 1;                         // old A[t+4] becomes A[t]
    }
}

// ---------------------------------------------------------------------------
// Chunked scan over s: phase A per-chunk sums, phase C prefix + local cumsum.
// ---------------------------------------------------------------------------
__global__ void scan_partial(const float* __restrict__ u, float* __restrict__ tot)
{
    const int j = ((blockIdx.x & 127) << 8) + threadIdx.x;
    const int c = blockIdx.x >> 7;
    const int s0 = c * CHUNK_LEN;
    const int s1 = min(s0 + CHUNK_LEN, SM1);
    float a = 0.f;
#pragma unroll 4
    for (int s = s0; s < s1; s++) a += u[(size_t)s * BD + j];
    tot[c * BD + j] = a;
}

__global__ void scan_final(const float* __restrict__ u,
                           const float* __restrict__ tot,
                           float* __restrict__ out)
{
    const int j = ((blockIdx.x & 127) << 8) + threadIdx.x;
    const int c = blockIdx.x >> 7;
    const int s0 = c * CHUNK_LEN;
    const int s1 = min(s0 + CHUNK_LEN, SM1);
    float acc = 0.f;
    for (int cc = 0; cc < c; cc++) acc += tot[cc * BD + j];
#pragma unroll 4
    for (int s = s0; s < s1; s++) {
        acc += u[(size_t)s * BD + j];
        out[(size_t)s * BD + j] = acc;
    }
}

extern "C" void kernel_launch(void* const* d_in, const int* in_sizes, int n_in,
                              void* d_out, int out_size)
{
    const float* src = (const float*)d_in[0];   // [S, B, D]
    const float* Wm  = (const float*)d_in[1];   // [D, D]
    const float* bm  = (const float*)d_in[2];   // [D]
    const float* Wb  = (const float*)d_in[3];   // [2D, D]
    const float* bb  = (const float*)d_in[4];   // [D]
    float* out = (float*)d_out;                 // [S-1, B, D]

    void *hp_v, *up_v, *tp_v;
    cudaGetSymbolAddress(&hp_v, g_h);
    cudaGetSymbolAddress(&up_v, g_u);
    cudaGetSymbolAddress(&tp_v, g_tot);
    float* hp = (float*)hp_v;
    float* up = (float*)up_v;
    float* tp = (float*)tp_v;

    const int smem_bytes = (3 * 128 * PAD) * sizeof(unsigned);   // 202752
    cudaFuncSetAttribute((const void*)gemm_map,
                         cudaFuncAttributeMaxDynamicSharedMemorySize, smem_bytes);
    cudaFuncSetAttribute((const void*)gemm_bracket,
                         cudaFuncAttributeMaxDynamicSharedMemorySize, smem_bytes);

    gemm_map<<<148, 256, smem_bytes>>>(src, Wm, bm, hp);
    gemm_bracket<<<148, 256, smem_bytes>>>(hp, Wb, bb, up);
    scan_partial<<<NCHUNK * (BD / 256), 256>>>(up, tp);
    scan_final<<<NCHUNK * (BD / 256), 256>>>(up, tp, out);
}

// round 5
// speedup vs baseline: 2.8123x; 2.0463x over previous
#include <cuda_runtime.h>
#include <cuda_fp16.h>
#include <cstdint>

#define S_DIM 2048
#define B_DIM 256
#define D_DIM 128
#define M_TOTAL (S_DIM * B_DIM)     // 524288 token rows
#define BD 32768                    // B*D scan lanes
#define SM1 2047
#define NJ 74                       // chain segments (chunks) per b-half
#define ROWB 272                    // smem row stride in bytes (136 halves)
#define TILEB (128 * ROWB)          // 34816 bytes per 128x128 fp16 tile

// Scratch
__device__ __half g_h[(size_t)M_TOTAL * 128];   // 134 MB
__device__ float  g_tot[NJ * 32768];            // per-chunk sums
__device__ float  g_ptot[NJ * 32768];           // exclusive prefixes

__device__ __forceinline__ uint32_t s2u(const void* p) {
    uint32_t a;
    asm("{ .reg .u64 t; cvta.to.shared.u64 t, %1; cvt.u32.u64 %0, t; }"
        : "=r"(a) : "l"(p));
    return a;
}

__device__ __forceinline__ uint32_t packh2(float a, float b) {
    __half2 h = __floats2half2_rn(a, b);
    return *(uint32_t*)&h;
}

#define LDSM4(r0, r1, r2, r3, addr)                                            \
    asm volatile("ldmatrix.sync.aligned.m8n8.x4.shared.b16 {%0,%1,%2,%3}, [%4];" \
                 : "=r"(r0), "=r"(r1), "=r"(r2), "=r"(r3) : "r"(addr))

#define MMA_F16(acc, a, b)                                                     \
    asm volatile("mma.sync.aligned.m16n8k16.row.col.f32.f16.f16.f32 "          \
                 "{%0,%1,%2,%3}, {%4,%5,%6,%7}, {%8,%9}, {%0,%1,%2,%3};"       \
                 : "+f"((acc)[0]), "+f"((acc)[1]), "+f"((acc)[2]), "+f"((acc)[3]) \
                 : "r"((a)[0]), "r"((a)[1]), "r"((a)[2]), "r"((a)[3]),         \
                   "r"((b)[0]), "r"((b)[1]))

// ---------------------------------------------------------------------------
// One 128x128 @ 128x128 accumulation pass.
// A tile smem [128 rows][136 halves]; W smem [128 n][136 k halves].
// Warp grid 4(M)x2(N): mb = (w&3)*32 (mt=2 x m16), nb = (w>>2)*64 (nt=8 x n8).
// ---------------------------------------------------------------------------
__device__ __forceinline__ void gemm_phase(uint32_t aBase, uint32_t bBase,
                                           int mb, int nb, int lane,
                                           float (&acc)[2][8][4])
{
    const uint32_t arow = aBase + (uint32_t)(mb + (lane & 15)) * ROWB
                        + (uint32_t)((lane >> 4) * 16);
    uint32_t brow[4];
#pragma unroll
    for (int q = 0; q < 4; q++)
        brow[q] = bBase
                + (uint32_t)(nb + q * 16 + ((lane & 7) | ((lane >> 4) << 3))) * ROWB
                + (uint32_t)(((lane >> 3) & 1) * 16);

#pragma unroll
    for (int ks = 0; ks < 8; ks++) {
        const uint32_t ko = ks * 32;          // 16 halves per kstep
        uint32_t a0[4], a1[4];
        LDSM4(a0[0], a0[1], a0[2], a0[3], arow + ko);
        LDSM4(a1[0], a1[1], a1[2], a1[3], arow + 16 * ROWB + ko);
        uint32_t bf[8][2];
#pragma unroll
        for (int q = 0; q < 4; q++) {
            uint32_t m0, m1, m2, m3;
            LDSM4(m0, m1, m2, m3, brow[q] + ko);
            bf[2 * q][0] = m0; bf[2 * q][1] = m1;
            bf[2 * q + 1][0] = m2; bf[2 * q + 1][1] = m3;
        }
#pragma unroll
        for (int nt = 0; nt < 8; nt++) {
            MMA_F16(acc[0][nt], a0, bf[nt]);
            MMA_F16(acc[1][nt], a1, bf[nt]);
        }
    }
}

// Stage a 128x128 fp32 tile -> 16B half-chunks in regs (8 x uint4 per thread).
__device__ __forceinline__ void stage_cvt(const float* __restrict__ base,
                                          int tid, uint4* st) {
#pragma unroll
    for (int i = 0; i < 8; i++) {
        int c = i * 256 + tid;               // 16B chunk id (2048 total)
        int row = c >> 4, col16 = c & 15;
        const float4* p = (const float4*)(base + row * 128 + col16 * 8);
        float4 f0 = p[0], f1 = p[1];
        uint4 v;
        v.x = packh2(f0.x, f0.y); v.y = packh2(f0.z, f0.w);
        v.z = packh2(f1.x, f1.y); v.w = packh2(f1.z, f1.w);
        st[i] = v;
    }
}

// Stage a 128x128 fp16 tile (copy).
__device__ __forceinline__ void stage_cpy(const __half* __restrict__ base,
                                          int tid, uint4* st) {
#pragma unroll
    for (int i = 0; i < 8; i++) {
        int c = i * 256 + tid;
        int row = c >> 4, col16 = c & 15;
        st[i] = *(const uint4*)(base + row * 128 + col16 * 8);
    }
}

__device__ __forceinline__ void sts_stage(char* sA, int tid, const uint4* st) {
#pragma unroll
    for (int i = 0; i < 8; i++) {
        int c = i * 256 + tid;
        int row = c >> 4, col16 = c & 15;
        *(uint4*)(sA + row * ROWB + col16 * 16) = st[i];
    }
}

// Load W[k][n] fp32 (128x128) -> smem [n][136 halves] (transposed, fp16).
__device__ __forceinline__ void load_w(const float* __restrict__ W, char* sW, int tid) {
    for (int idx = tid; idx < 16384; idx += 256) {
        int k = idx >> 7, n = idx & 127;
        *(__half*)(sW + n * ROWB + k * 2) = __float2half_rn(W[idx]);
    }
}

// ---------------------------------------------------------------------------
// Persistent map GEMM: h = relu(src @ Wm + bm) -> fp16
// smem: bias(512) | W(34816) | A0 | A1   = 104960 B
// ---------------------------------------------------------------------------
__global__ void __launch_bounds__(256, 1)
gemm_map(const float* __restrict__ A, const float* __restrict__ W,
         const float* __restrict__ bias, __half* __restrict__ H)
{
    extern __shared__ char smem[];
    float* sbias = (float*)smem;
    char* sW  = smem + 512;
    char* sA0 = sW + TILEB;
    char* sA1 = sA0 + TILEB;

    const int tid = threadIdx.x;
    const int lane = tid & 31, w = tid >> 5;
    const int mb = (w & 3) * 32, nb = (w >> 2) * 64;
    const int grp = lane >> 2, thr = lane & 3;
    const int bid = blockIdx.x;
    const int base = bid * 27 + (bid < 100 ? bid : 100);
    const int cnt  = 27 + (bid < 100 ? 1 : 0);

    load_w(W, sW, tid);
    if (tid < 128) sbias[tid] = bias[tid];
    {
        uint4 st[8];
        stage_cvt(A + (size_t)base * 16384, tid, st);
        sts_stage(sA0, tid, st);
    }
    __syncthreads();

    float br[8][2];
#pragma unroll
    for (int nt = 0; nt < 8; nt++) {
        int c = nb + nt * 8 + 2 * thr;
        br[nt][0] = sbias[c]; br[nt][1] = sbias[c + 1];
    }

    const uint32_t sWu = s2u(sW), sA0u = s2u(sA0), sA1u = s2u(sA1);
    int cur = 0;
    for (int it = 0; it < cnt; it++) {
        const bool pref = (it + 1 < cnt);
        uint4 st[8];
        if (pref) stage_cvt(A + (size_t)(base + it + 1) * 16384, tid, st);

        float acc[2][8][4];
#pragma unroll
        for (int mt = 0; mt < 2; mt++)
#pragma unroll
            for (int nt = 0; nt < 8; nt++)
#pragma unroll
                for (int q = 0; q < 4; q++) acc[mt][nt][q] = 0.f;

        gemm_phase(cur ? sA1u : sA0u, sWu, mb, nb, lane, acc);

        const size_t row0 = (size_t)(base + it) * 128;
#pragma unroll
        for (int mt = 0; mt < 2; mt++) {
#pragma unroll
            for (int nt = 0; nt < 8; nt++) {
                int r = mb + mt * 16 + grp;
                int c = nb + nt * 8 + 2 * thr;
                uint32_t v0 = packh2(fmaxf(acc[mt][nt][0] + br[nt][0], 0.f),
                                     fmaxf(acc[mt][nt][1] + br[nt][1], 0.f));
                uint32_t v1 = packh2(fmaxf(acc[mt][nt][2] + br[nt][0], 0.f),
                                     fmaxf(acc[mt][nt][3] + br[nt][1], 0.f));
                *(uint32_t*)(H + (row0 + r) * 128 + c) = v0;
                *(uint32_t*)(H + (row0 + r + 8) * 128 + c) = v1;
            }
        }

        __syncthreads();
        if (pref) sts_stage(cur ? sA0 : sA1, tid, st);
        __syncthreads();
        cur ^= 1;
    }
}

// ---------------------------------------------------------------------------
// Persistent fused bracket + local cumsum:
//   u[s] = h[s] + relu(h[s]@Wb1 + h[s+1]@Wb2 + bb)   (per tile = one b-half)
//   out[s] = running sum of u within this CTA's chain; chain totals -> g_tot.
// Chain (res, j): tiles t = res + 2*(i0+it), s = i0+it (consecutive!).
// smem: bias | W1 | W2 | B0 | B1 | B2 = 174592 B
// ---------------------------------------------------------------------------
__global__ void __launch_bounds__(256, 1)
gemm_bracket(const __half* __restrict__ H, const float* __restrict__ Wb,
             const float* __restrict__ bb, float* __restrict__ out,
             float* __restrict__ tot)
{
    extern __shared__ char smem[];
    float* sbias = (float*)smem;
    char* sW1 = smem + 512;
    char* sW2 = sW1 + TILEB;
    char* b0 = sW2 + TILEB;
    char* b1 = b0 + TILEB;
    char* b2 = b1 + TILEB;

    const int tid = threadIdx.x;
    const int lane = tid & 31, w = tid >> 5;
    const int mb = (w & 3) * 32, nb = (w >> 2) * 64;
    const int grp = lane >> 2, thr = lane & 3;
    const int bid = blockIdx.x;
    const int res = bid & 1;
    const int j   = bid >> 1;                       // 0..73
    const int i0  = j * 27 + (j < 49 ? j : 49);     // 49 chains of 28, 25 of 27
    const int cnt = 27 + (j < 49 ? 1 : 0);

    load_w(Wb, sW1, tid);
    load_w(Wb + 16384, sW2, tid);
    if (tid < 128) sbias[tid] = bb[tid];

    const size_t t0 = (size_t)res + 2 * (size_t)i0;
    {
        uint4 st[8];
        stage_cpy(H + t0 * 16384, tid, st);
        sts_stage(b0, tid, st);
        stage_cpy(H + (t0 + 2) * 16384, tid, st);
        sts_stage(b1, tid, st);
    }
    __syncthreads();

    float br[8][2];
#pragma unroll
    for (int nt = 0; nt < 8; nt++) {
        int c = nb + nt * 8 + 2 * thr;
        br[nt][0] = sbias[c]; br[nt][1] = sbias[c + 1];
    }

    const uint32_t sW1u = s2u(sW1), sW2u = s2u(sW2);
    char* bt  = b0;   // A[t]
    char* bt2 = b1;   // A[t+2]
    char* bpr = b2;   // prefetch dest A[t+4]

    float racc[2][8][4];
#pragma unroll
    for (int mt = 0; mt < 2; mt++)
#pragma unroll
        for (int nt = 0; nt < 8; nt++)
#pragma unroll
            for (int q = 0; q < 4; q++) racc[mt][nt][q] = 0.f;

    for (int it = 0; it < cnt; it++) {
        const size_t t = (size_t)res + 2 * (size_t)(i0 + it);
        const bool pref = (it + 1 < cnt);
        uint4 st[8];
        if (pref) stage_cpy(H + (t + 4) * 16384, tid, st);

        float acc[2][8][4];
#pragma unroll
        for (int mt = 0; mt < 2; mt++)
#pragma unroll
            for (int nt = 0; nt < 8; nt++)
#pragma unroll
                for (int q = 0; q < 4; q++) acc[mt][nt][q] = 0.f;

        gemm_phase(s2u(bt),  sW1u, mb, nb, lane, acc);   // h[s]   @ Wb1
        gemm_phase(s2u(bt2), sW2u, mb, nb, lane, acc);   // h[s+1] @ Wb2

        // epilogue: racc += h + relu(acc + bb); out = racc
        const size_t obase = (size_t)(i0 + it) * BD + (size_t)res * 16384;
#pragma unroll
        for (int mt = 0; mt < 2; mt++) {
#pragma unroll
            for (int nt = 0; nt < 8; nt++) {
                int r = mb + mt * 16 + grp;
                int c = nb + nt * 8 + 2 * thr;
                float2 h0 = __half22float2(*(__half2*)(bt + r * ROWB + c * 2));
                float2 h1 = __half22float2(*(__half2*)(bt + (r + 8) * ROWB + c * 2));
                racc[mt][nt][0] += h0.x + fmaxf(acc[mt][nt][0] + br[nt][0], 0.f);
                racc[mt][nt][1] += h0.y + fmaxf(acc[mt][nt][1] + br[nt][1], 0.f);
                racc[mt][nt][2] += h1.x + fmaxf(acc[mt][nt][2] + br[nt][0], 0.f);
                racc[mt][nt][3] += h1.y + fmaxf(acc[mt][nt][3] + br[nt][1], 0.f);
                *(float2*)(out + obase + r * 128 + c) =
                    make_float2(racc[mt][nt][0], racc[mt][nt][1]);
                *(float2*)(out + obase + (r + 8) * 128 + c) =
                    make_float2(racc[mt][nt][2], racc[mt][nt][3]);
            }
        }

        __syncthreads();
        if (pref) sts_stage(bpr, tid, st);
        __syncthreads();
        char* tmp = bt; bt = bt2; bt2 = bpr; bpr = tmp;
    }

    // chain totals
    float* tbase = tot + (size_t)j * 32768 + (size_t)res * 16384;
#pragma unroll
    for (int mt = 0; mt < 2; mt++) {
#pragma unroll
        for (int nt = 0; nt < 8; nt++) {
            int r = mb + mt * 16 + grp;
            int c = nb + nt * 8 + 2 * thr;
            *(float2*)(tbase + r * 128 + c) =
                make_float2(racc[mt][nt][0], racc[mt][nt][1]);
            *(float2*)(tbase + (r + 8) * 128 + c) =
                make_float2(racc[mt][nt][2], racc[mt][nt][3]);
        }
    }
}

// Exclusive prefix over the 74 chunk totals (per lane).
__global__ void scan_prefix(const float* __restrict__ tot, float* __restrict__ ptot)
{
    const int lane = blockIdx.x * 256 + threadIdx.x;    // 0..32767
    float a = 0.f;
#pragma unroll 2
    for (int jj = 0; jj < NJ; jj++) {
        float v = tot[(size_t)jj * 32768 + lane];
        ptot[(size_t)jj * 32768 + lane] = a;
        a += v;
    }
}

// out[s,b,d] += ptot[chunk(s)][lane(b,d)]   (float4 per thread)
__global__ void fixup(float* __restrict__ out, const float* __restrict__ ptot)
{
    const size_t g = (size_t)blockIdx.x * 256 + threadIdx.x;   // float4 id
    const int s = (int)(g >> 13);
    const int rem = (int)(g & 8191);
    const int jj = (s < 1372) ? (s / 28) : (49 + (s - 1372) / 27);
    float4 p = ((const float4*)ptot)[(size_t)jj * 8192 + rem];
    float4 o = ((float4*)out)[g];
    o.x += p.x; o.y += p.y; o.z += p.z; o.w += p.w;
    ((float4*)out)[g] = o;
}

extern "C" void kernel_launch(void* const* d_in, const int* in_sizes, int n_in,
                              void* d_out, int out_size)
{
    const float* src = (const float*)d_in[0];   // [S, B, D]
    const float* Wm  = (const float*)d_in[1];   // [D, D]
    const float* bm  = (const float*)d_in[2];   // [D]
    const float* Wb  = (const float*)d_in[3];   // [2D, D]
    const float* bb  = (const float*)d_in[4];   // [D]
    float* out = (float*)d_out;                 // [S-1, B, D]

    void *hp_v, *tp_v, *pp_v;
    cudaGetSymbolAddress(&hp_v, g_h);
    cudaGetSymbolAddress(&tp_v, g_tot);
    cudaGetSymbolAddress(&pp_v, g_ptot);
    __half* hp = (__half*)hp_v;
    float* tp = (float*)tp_v;
    float* pp = (float*)pp_v;

    const int smem_map = 512 + 3 * TILEB;   // 104960
    const int smem_brk = 512 + 5 * TILEB;   // 174592
    cudaFuncSetAttribute((const void*)gemm_map,
                         cudaFuncAttributeMaxDynamicSharedMemorySize, smem_map);
    cudaFuncSetAttribute((const void*)gemm_bracket,
                         cudaFuncAttributeMaxDynamicSharedMemorySize, smem_brk);

    gemm_map<<<148, 256, smem_map>>>(src, Wm, bm, hp);
    gemm_bracket<<<148, 256, smem_brk>>>(hp, Wb, bb, out, tp);
    scan_prefix<<<128, 256>>>(tp, pp);
    fixup<<<65504, 256>>>(out, pp);         // 2047 * 8192 / 256
}

// round 6
// speedup vs baseline: 2.9950x; 1.0649x over previous
#include <cuda_runtime.h>
#include <cuda_fp16.h>
#include <cstdint>

#define S_DIM 2048
#define B_DIM 256
#define D_DIM 128
#define M_TOTAL (S_DIM * B_DIM)     // 524288 token rows
#define BD 32768                    // B*D scan lanes
#define SM1 2047
#define NJ 74                       // chain chunks per b-half (49x28 + 25x27)
#define ROWB 272                    // smem row stride in bytes (136 halves)
#define TILEB (128 * ROWB)          // 34816 bytes per 128x128 fp16 tile

// Scratch
__device__ __half g_h[(size_t)M_TOTAL * 128];      // 134 MB : h fp16
__device__ __half g_uloc[(size_t)SM1 * BD];        // 134 MB : local cumsum fp16
__device__ float  g_tot[NJ * 32768];               // per-chunk sums
__device__ float  g_ptot[NJ * 32768];              // exclusive prefixes

__device__ __forceinline__ uint32_t s2u(const void* p) {
    uint32_t a;
    asm("{ .reg .u64 t; cvta.to.shared.u64 t, %1; cvt.u32.u64 %0, t; }"
        : "=r"(a) : "l"(p));
    return a;
}

__device__ __forceinline__ uint32_t packh2(float a, float b) {
    __half2 h = __floats2half2_rn(a, b);
    return *(uint32_t*)&h;
}

#define LDSM4(r0, r1, r2, r3, addr)                                            \
    asm volatile("ldmatrix.sync.aligned.m8n8.x4.shared.b16 {%0,%1,%2,%3}, [%4];" \
                 : "=r"(r0), "=r"(r1), "=r"(r2), "=r"(r3) : "r"(addr))

#define MMA_F16(acc, a, b)                                                     \
    asm volatile("mma.sync.aligned.m16n8k16.row.col.f32.f16.f16.f32 "          \
                 "{%0,%1,%2,%3}, {%4,%5,%6,%7}, {%8,%9}, {%0,%1,%2,%3};"       \
                 : "+f"((acc)[0]), "+f"((acc)[1]), "+f"((acc)[2]), "+f"((acc)[3]) \
                 : "r"((a)[0]), "r"((a)[1]), "r"((a)[2]), "r"((a)[3]),         \
                   "r"((b)[0]), "r"((b)[1]))

// ---------------------------------------------------------------------------
// One 128x128 @ 128x128 accumulation pass (A smem, W smem [n][k] fp16).
// Warp grid 4(M)x2(N): mb=(w&3)*32, nb=(w>>2)*64.
// ---------------------------------------------------------------------------
__device__ __forceinline__ void gemm_phase(uint32_t aBase, uint32_t bBase,
                                           int mb, int nb, int lane,
                                           float (&acc)[2][8][4])
{
    const uint32_t arow = aBase + (uint32_t)(mb + (lane & 15)) * ROWB
                        + (uint32_t)((lane >> 4) * 16);
    uint32_t brow[4];
#pragma unroll
    for (int q = 0; q < 4; q++)
        brow[q] = bBase
                + (uint32_t)(nb + q * 16 + ((lane & 7) | ((lane >> 4) << 3))) * ROWB
                + (uint32_t)(((lane >> 3) & 1) * 16);

#pragma unroll
    for (int ks = 0; ks < 8; ks++) {
        const uint32_t ko = ks * 32;
        uint32_t a0[4], a1[4];
        LDSM4(a0[0], a0[1], a0[2], a0[3], arow + ko);
        LDSM4(a1[0], a1[1], a1[2], a1[3], arow + 16 * ROWB + ko);
        uint32_t bf[8][2];
#pragma unroll
        for (int q = 0; q < 4; q++) {
            uint32_t m0, m1, m2, m3;
            LDSM4(m0, m1, m2, m3, brow[q] + ko);
            bf[2 * q][0] = m0; bf[2 * q][1] = m1;
            bf[2 * q + 1][0] = m2; bf[2 * q + 1][1] = m3;
        }
#pragma unroll
        for (int nt = 0; nt < 8; nt++) {
            MMA_F16(acc[0][nt], a0, bf[nt]);
            MMA_F16(acc[1][nt], a1, bf[nt]);
        }
    }
}

// Stage a 128x128 fp32 tile -> fp16 chunks in regs (8 x uint4 per thread).
__device__ __forceinline__ void stage_cvt(const float* __restrict__ base,
                                          int tid, uint4* st) {
#pragma unroll
    for (int i = 0; i < 8; i++) {
        int c = i * 256 + tid;
        int row = c >> 4, col16 = c & 15;
        const float4* p = (const float4*)(base + row * 128 + col16 * 8);
        float4 f0 = p[0], f1 = p[1];
        uint4 v;
        v.x = packh2(f0.x, f0.y); v.y = packh2(f0.z, f0.w);
        v.z = packh2(f1.x, f1.y); v.w = packh2(f1.z, f1.w);
        st[i] = v;
    }
}

__device__ __forceinline__ void stage_cpy(const __half* __restrict__ base,
                                          int tid, uint4* st) {
#pragma unroll
    for (int i = 0; i < 8; i++) {
        int c = i * 256 + tid;
        int row = c >> 4, col16 = c & 15;
        st[i] = *(const uint4*)(base + row * 128 + col16 * 8);
    }
}

__device__ __forceinline__ void sts_stage(char* sA, int tid, const uint4* st) {
#pragma unroll
    for (int i = 0; i < 8; i++) {
        int c = i * 256 + tid;
        int row = c >> 4, col16 = c & 15;
        *(uint4*)(sA + row * ROWB + col16 * 16) = st[i];
    }
}

// Load W[k][n] fp32 (128x128) -> smem [n][k] fp16 (transposed).
__device__ __forceinline__ void load_w(const float* __restrict__ W, char* sW, int tid) {
    for (int idx = tid; idx < 16384; idx += 256) {
        int k = idx >> 7, n = idx & 127;
        *(__half*)(sW + n * ROWB + k * 2) = __float2half_rn(W[idx]);
    }
}

// ---------------------------------------------------------------------------
// Persistent map GEMM: h = relu(src @ Wm + bm) -> fp16
// ---------------------------------------------------------------------------
__global__ void __launch_bounds__(256, 1)
gemm_map(const float* __restrict__ A, const float* __restrict__ W,
         const float* __restrict__ bias, __half* __restrict__ H)
{
    extern __shared__ char smem[];
    float* sbias = (float*)smem;
    char* sW  = smem + 512;
    char* sA0 = sW + TILEB;
    char* sA1 = sA0 + TILEB;

    const int tid = threadIdx.x;
    const int lane = tid & 31, w = tid >> 5;
    const int mb = (w & 3) * 32, nb = (w >> 2) * 64;
    const int grp = lane >> 2, thr = lane & 3;
    const int bid = blockIdx.x;
    const int base = bid * 27 + (bid < 100 ? bid : 100);
    const int cnt  = 27 + (bid < 100 ? 1 : 0);

    load_w(W, sW, tid);
    if (tid < 128) sbias[tid] = bias[tid];
    {
        uint4 st[8];
        stage_cvt(A + (size_t)base * 16384, tid, st);
        sts_stage(sA0, tid, st);
    }
    __syncthreads();

    float br[8][2];
#pragma unroll
    for (int nt = 0; nt < 8; nt++) {
        int c = nb + nt * 8 + 2 * thr;
        br[nt][0] = sbias[c]; br[nt][1] = sbias[c + 1];
    }

    const uint32_t sWu = s2u(sW), sA0u = s2u(sA0), sA1u = s2u(sA1);
    int cur = 0;
    for (int it = 0; it < cnt; it++) {
        const bool pref = (it + 1 < cnt);
        uint4 st[8];
        if (pref) stage_cvt(A + (size_t)(base + it + 1) * 16384, tid, st);

        float acc[2][8][4];
#pragma unroll
        for (int mt = 0; mt < 2; mt++)
#pragma unroll
            for (int nt = 0; nt < 8; nt++)
#pragma unroll
                for (int q = 0; q < 4; q++) acc[mt][nt][q] = 0.f;

        gemm_phase(cur ? sA1u : sA0u, sWu, mb, nb, lane, acc);

        const size_t row0 = (size_t)(base + it) * 128;
#pragma unroll
        for (int mt = 0; mt < 2; mt++) {
#pragma unroll
            for (int nt = 0; nt < 8; nt++) {
                int r = mb + mt * 16 + grp;
                int c = nb + nt * 8 + 2 * thr;
                uint32_t v0 = packh2(fmaxf(acc[mt][nt][0] + br[nt][0], 0.f),
                                     fmaxf(acc[mt][nt][1] + br[nt][1], 0.f));
                uint32_t v1 = packh2(fmaxf(acc[mt][nt][2] + br[nt][0], 0.f),
                                     fmaxf(acc[mt][nt][3] + br[nt][1], 0.f));
                *(uint32_t*)(H + (row0 + r) * 128 + c) = v0;
                *(uint32_t*)(H + (row0 + r + 8) * 128 + c) = v1;
            }
        }

        __syncthreads();
        if (pref) sts_stage(cur ? sA0 : sA1, tid, st);
        __syncthreads();
        cur ^= 1;
    }
}

// ---------------------------------------------------------------------------
// Persistent fused bracket + local cumsum:
//   u[s] = h[s] + relu(h[s]@Wb1 + h[s+1]@Wb2 + bb)
//   uloc[s] = running fp16 cumsum within chain; chain totals -> g_tot (fp32).
// ---------------------------------------------------------------------------
__global__ void __launch_bounds__(256, 1)
gemm_bracket(const __half* __restrict__ H, const float* __restrict__ Wb,
             const float* __restrict__ bb, __half* __restrict__ uloc,
             float* __restrict__ tot)
{
    extern __shared__ char smem[];
    float* sbias = (float*)smem;
    char* sW1 = smem + 512;
    char* sW2 = sW1 + TILEB;
    char* b0 = sW2 + TILEB;
    char* b1 = b0 + TILEB;
    char* b2 = b1 + TILEB;

    const int tid = threadIdx.x;
    const int lane = tid & 31, w = tid >> 5;
    const int mb = (w & 3) * 32, nb = (w >> 2) * 64;
    const int grp = lane >> 2, thr = lane & 3;
    const int bid = blockIdx.x;
    const int res = bid & 1;
    const int j   = bid >> 1;                       // 0..73
    const int i0  = j * 27 + (j < 49 ? j : 49);
    const int cnt = 27 + (j < 49 ? 1 : 0);

    load_w(Wb, sW1, tid);
    load_w(Wb + 16384, sW2, tid);
    if (tid < 128) sbias[tid] = bb[tid];

    const size_t t0 = (size_t)res + 2 * (size_t)i0;
    {
        uint4 st[8];
        stage_cpy(H + t0 * 16384, tid, st);
        sts_stage(b0, tid, st);
        stage_cpy(H + (t0 + 2) * 16384, tid, st);
        sts_stage(b1, tid, st);
    }
    __syncthreads();

    float br[8][2];
#pragma unroll
    for (int nt = 0; nt < 8; nt++) {
        int c = nb + nt * 8 + 2 * thr;
        br[nt][0] = sbias[c]; br[nt][1] = sbias[c + 1];
    }

    const uint32_t sW1u = s2u(sW1), sW2u = s2u(sW2);
    char* bt  = b0;
    char* bt2 = b1;
    char* bpr = b2;

    float racc[2][8][4];
#pragma unroll
    for (int mt = 0; mt < 2; mt++)
#pragma unroll
        for (int nt = 0; nt < 8; nt++)
#pragma unroll
            for (int q = 0; q < 4; q++) racc[mt][nt][q] = 0.f;

    for (int it = 0; it < cnt; it++) {
        const size_t t = (size_t)res + 2 * (size_t)(i0 + it);
        const bool pref = (it + 1 < cnt);
        uint4 st[8];
        if (pref) stage_cpy(H + (t + 4) * 16384, tid, st);

        float acc[2][8][4];
#pragma unroll
        for (int mt = 0; mt < 2; mt++)
#pragma unroll
            for (int nt = 0; nt < 8; nt++)
#pragma unroll
                for (int q = 0; q < 4; q++) acc[mt][nt][q] = 0.f;

        gemm_phase(s2u(bt),  sW1u, mb, nb, lane, acc);   // h[s]   @ Wb1
        gemm_phase(s2u(bt2), sW2u, mb, nb, lane, acc);   // h[s+1] @ Wb2

        // epilogue: racc += h + relu(acc + bb); uloc = fp16(racc)
        const size_t obase = (size_t)(i0 + it) * BD + (size_t)res * 16384;
#pragma unroll
        for (int mt = 0; mt < 2; mt++) {
#pragma unroll
            for (int nt = 0; nt < 8; nt++) {
                int r = mb + mt * 16 + grp;
                int c = nb + nt * 8 + 2 * thr;
                float2 h0 = __half22float2(*(__half2*)(bt + r * ROWB + c * 2));
                float2 h1 = __half22float2(*(__half2*)(bt + (r + 8) * ROWB + c * 2));
                racc[mt][nt][0] += h0.x + fmaxf(acc[mt][nt][0] + br[nt][0], 0.f);
                racc[mt][nt][1] += h0.y + fmaxf(acc[mt][nt][1] + br[nt][1], 0.f);
                racc[mt][nt][2] += h1.x + fmaxf(acc[mt][nt][2] + br[nt][0], 0.f);
                racc[mt][nt][3] += h1.y + fmaxf(acc[mt][nt][3] + br[nt][1], 0.f);
                *(uint32_t*)(uloc + obase + r * 128 + c) =
                    packh2(racc[mt][nt][0], racc[mt][nt][1]);
                *(uint32_t*)(uloc + obase + (r + 8) * 128 + c) =
                    packh2(racc[mt][nt][2], racc[mt][nt][3]);
            }
        }

        __syncthreads();
        if (pref) sts_stage(bpr, tid, st);
        __syncthreads();
        char* tmp = bt; bt = bt2; bt2 = bpr; bpr = tmp;
    }

    // chain totals (fp32, exact racc)
    float* tbase = tot + (size_t)j * 32768 + (size_t)res * 16384;
#pragma unroll
    for (int mt = 0; mt < 2; mt++) {
#pragma unroll
        for (int nt = 0; nt < 8; nt++) {
            int r = mb + mt * 16 + grp;
            int c = nb + nt * 8 + 2 * thr;
            *(float2*)(tbase + r * 128 + c) =
                make_float2(racc[mt][nt][0], racc[mt][nt][1]);
            *(float2*)(tbase + (r + 8) * 128 + c) =
                make_float2(racc[mt][nt][2], racc[mt][nt][3]);
        }
    }
}

// Exclusive prefix over the 74 chunk totals (per lane).
__global__ void scan_prefix(const float* __restrict__ tot, float* __restrict__ ptot)
{
    const int lane = blockIdx.x * 256 + threadIdx.x;
    float a = 0.f;
#pragma unroll 2
    for (int jj = 0; jj < NJ; jj++) {
        float v = tot[(size_t)jj * 32768 + lane];
        ptot[(size_t)jj * 32768 + lane] = a;
        a += v;
    }
}

// out[s,lane] = float(uloc[s,lane]) + ptot[chunk(s)][lane]; 8 lanes per thread.
__global__ void fixup(const __half* __restrict__ uloc,
                      const float* __restrict__ ptot,
                      float* __restrict__ out)
{
    const size_t g = (size_t)blockIdx.x * 256 + threadIdx.x;   // 8-lane group id
    const int s = (int)(g >> 12);                              // 4096 groups per s
    const int rem = (int)(g & 4095);
    const int jj = (s < 1372) ? (s / 28) : (49 + (s - 1372) / 27);

    uint4 u = ((const uint4*)(uloc + (size_t)s * BD))[rem];
    const float4* pp = (const float4*)(ptot + (size_t)jj * 32768) + rem * 2;
    float4 p0 = pp[0], p1 = pp[1];

    float2 a = __half22float2(*(__half2*)&u.x);
    float2 b = __half22float2(*(__half2*)&u.y);
    float2 c = __half22float2(*(__half2*)&u.z);
    float2 d = __half22float2(*(__half2*)&u.w);

    float4 o0 = make_float4(a.x + p0.x, a.y + p0.y, b.x + p0.z, b.y + p0.w);
    float4 o1 = make_float4(c.x + p1.x, c.y + p1.y, d.x + p1.z, d.y + p1.w);

    float4* op = (float4*)(out + (size_t)s * BD) + rem * 2;
    op[0] = o0;
    op[1] = o1;
}

extern "C" void kernel_launch(void* const* d_in, const int* in_sizes, int n_in,
                              void* d_out, int out_size)
{
    const float* src = (const float*)d_in[0];   // [S, B, D]
    const float* Wm  = (const float*)d_in[1];   // [D, D]
    const float* bm  = (const float*)d_in[2];   // [D]
    const float* Wb  = (const float*)d_in[3];   // [2D, D]
    const float* bb  = (const float*)d_in[4];   // [D]
    float* out = (float*)d_out;                 // [S-1, B, D]

    void *hp_v, *ul_v, *tp_v, *pp_v;
    cudaGetSymbolAddress(&hp_v, g_h);
    cudaGetSymbolAddress(&ul_v, g_uloc);
    cudaGetSymbolAddress(&tp_v, g_tot);
    cudaGetSymbolAddress(&pp_v, g_ptot);
    __half* hp = (__half*)hp_v;
    __half* ul = (__half*)ul_v;
    float* tp = (float*)tp_v;
    float* pp = (float*)pp_v;

    const int smem_map = 512 + 3 * TILEB;   // 104960
    const int smem_brk = 512 + 5 * TILEB;   // 174592
    cudaFuncSetAttribute((const void*)gemm_map,
                         cudaFuncAttributeMaxDynamicSharedMemorySize, smem_map);
    cudaFuncSetAttribute((const void*)gemm_bracket,
                         cudaFuncAttributeMaxDynamicSharedMemorySize, smem_brk);

    gemm_map<<<148, 256, smem_map>>>(src, Wm, bm, hp);
    gemm_bracket<<<148, 256, smem_brk>>>(hp, Wb, bb, ul, tp);
    scan_prefix<<<128, 256>>>(tp, pp);
    fixup<<<32752, 256>>>(ul, pp, out);     // 2047 * 4096 / 256
}